// round 1
// baseline (speedup 1.0000x reference)
#include <cuda_runtime.h>

// WeatherDifferentiatedAttention — fully fused, one CTA per (b,t) sequence.
// Pipeline per sequence: proj+LN (turbine, weather) -> cross-attn -> QKV ->
// 4-head self-attn -> attn_out -> out_proj + residual.

constexpr int NTHR = 512;
constexpr int NWARP = 16;
constexpr int NT = 200, NW = 100, CM = 256, DH = 64, NH = 4, HD = 16;

// SMEM pool layout (float offsets). Regions are overlaid per stage.
constexpr int OFF_X = 0;                 // 12800 : x / q / o      [200][64]
constexpr int OFF_K = 12800;             // 13000 : h_w / k        [.][65]
constexpr int OFF_V = OFF_K + 13000;     // 13000 : h_t / v        [.][65]
constexpr int OFF_W = OFF_V + 13000;     // 12352 : staged weights
constexpr int OFF_P = OFF_W + 12352;     // 3200  : per-warp probs / staging
constexpr int OFF_S = OFF_P + 3200;      // 1024  : per-warp row staging
constexpr int SMEM_F = OFF_S + 1024;     // 55376 floats = 221504 bytes
// stage-5 overlays (attn_out^T and out_proj^T live where k/v used to be)
constexpr int OFF_AO = OFF_K;            // [64][65]  = 4160
constexpr int OFF_OP = OFF_K + 4160;     // [64][257] = 16448 (spans K+V)

__device__ __forceinline__ float wsum(float v) {
#pragma unroll
    for (int o = 16; o; o >>= 1) v += __shfl_xor_sync(0xffffffffu, v, o);
    return v;
}
__device__ __forceinline__ float wmax(float v) {
#pragma unroll
    for (int o = 16; o; o >>= 1) v = fmaxf(v, __shfl_xor_sync(0xffffffffu, v, o));
    return v;
}

__global__ __launch_bounds__(NTHR, 1) void wda_kernel(
    const float* __restrict__ turb, const float* __restrict__ weath,
    const float* __restrict__ w_t,  const float* __restrict__ b_t,
    const float* __restrict__ w_w,  const float* __restrict__ b_w,
    const float* __restrict__ g_t,  const float* __restrict__ be_t,
    const float* __restrict__ g_w,  const float* __restrict__ be_w,
    const float* __restrict__ w_qkv,const float* __restrict__ b_qkv,
    const float* __restrict__ w_ao, const float* __restrict__ b_ao,
    const float* __restrict__ w_op, const float* __restrict__ b_op,
    float* __restrict__ out)
{
    extern __shared__ float sm[];
    const int tid  = threadIdx.x;
    const int warp = tid >> 5, lane = tid & 31;
    const int d0 = 2 * lane, d1 = d0 + 1;
    const size_t s = blockIdx.x;
    const float* turb_s  = turb  + s * (size_t)(NT * CM);
    const float* weath_s = weath + s * (size_t)(NW * CM);
    float*       out_s   = out   + s * (size_t)(NT * CM);

    // ================= Stage 1: h_t = LN(turb@w_t^T + b), h_w likewise ====
    for (int src = 0; src < 2; ++src) {
        const float* inp = src ? weath_s : turb_s;
        const float* Wg  = src ? w_w  : w_t;
        const float* bg  = src ? b_w  : b_t;
        const float* gg  = src ? g_w  : g_t;
        const float* beg = src ? be_w : be_t;
        const int rows   = src ? NW : NT;
        const int rows2  = rows >> 1;
        float* hbase = sm + (src ? OFF_K : OFF_V);

        for (int ch = 0; ch < 2; ++ch) {
            __syncthreads();
            // stage weight chunk transposed: wT[c][d], stride 65 (conflict-free reads)
            for (int idx = tid; idx < 128 * 64; idx += NTHR) {
                int d = idx >> 7, c = idx & 127;
                sm[OFF_W + c * 65 + d] = Wg[d * 256 + ch * 128 + c];
            }
            __syncthreads();
            // each warp computes two rows (r, r+rows2), 2 outputs per lane
            for (int r = warp; r < rows2; r += NWARP) {
                float* rs = sm + OFF_P + warp * 256;
                for (int j = lane; j < 128; j += 32) {
                    rs[j]       = inp[(size_t)r * CM + ch * 128 + j];
                    rs[128 + j] = inp[(size_t)(r + rows2) * CM + ch * 128 + j];
                }
                __syncwarp();
                float a0 = 0.f, a1 = 0.f, a2 = 0.f, a3 = 0.f;
#pragma unroll 4
                for (int c = 0; c < 128; ++c) {
                    float wv0 = sm[OFF_W + c * 65 + d0];
                    float wv1 = sm[OFF_W + c * 65 + d1];
                    float x0 = rs[c], x1 = rs[128 + c];
                    a0 = fmaf(x0, wv0, a0); a1 = fmaf(x0, wv1, a1);
                    a2 = fmaf(x1, wv0, a2); a3 = fmaf(x1, wv1, a3);
                }
                float* h0 = hbase + r * 65;
                float* h1 = hbase + (r + rows2) * 65;
                if (ch == 0) { h0[d0] = a0; h0[d1] = a1; h1[d0] = a2; h1[d1] = a3; }
                else         { h0[d0] += a0; h0[d1] += a1; h1[d0] += a2; h1[d1] += a3; }
                __syncwarp();
            }
        }
        __syncthreads();  // rows for LN may have been accumulated by another warp
        // LayerNorm (+bias) in place
        const float bb0 = bg[d0],  bb1 = bg[d1];
        const float gg0 = gg[d0],  gg1 = gg[d1];
        const float eb0 = beg[d0], eb1 = beg[d1];
        for (int r = warp; r < rows; r += NWARP) {
            float* hr = hbase + r * 65;
            float v0 = hr[d0] + bb0, v1 = hr[d1] + bb1;
            float mu = wsum(v0 + v1) * (1.f / DH);
            float s2 = wsum(v0 * v0 + v1 * v1) * (1.f / DH);
            float rstd = rsqrtf(s2 - mu * mu + 1e-5f);
            hr[d0] = (v0 - mu) * rstd * gg0 + eb0;
            hr[d1] = (v1 - mu) * rstd * gg1 + eb1;
        }
    }
    __syncthreads();

    // ================= Stage 2: cross-attention, x = softmax(h_t h_w^T/8) h_w
    for (int r = warp; r < NT; r += NWARP) {
        const float* ht = sm + OFF_V + r * 65;
        int moff[4];
#pragma unroll
        for (int mi = 0; mi < 4; ++mi) {
            int m = lane + 32 * mi;
            moff[mi] = OFF_K + (m < NW ? m : NW - 1) * 65;
        }
        float a[4] = {0.f, 0.f, 0.f, 0.f};
#pragma unroll 4
        for (int d = 0; d < DH; ++d) {
            float htd = ht[d];
#pragma unroll
            for (int mi = 0; mi < 4; ++mi) a[mi] = fmaf(htd, sm[moff[mi] + d], a[mi]);
        }
        float mx = -1e30f;
#pragma unroll
        for (int mi = 0; mi < 4; ++mi) {
            a[mi] = (lane + 32 * mi < NW) ? a[mi] * 0.125f : -1e30f;
            mx = fmaxf(mx, a[mi]);
        }
        mx = wmax(mx);
        float ss = 0.f;
#pragma unroll
        for (int mi = 0; mi < 4; ++mi) {
            a[mi] = (lane + 32 * mi < NW) ? __expf(a[mi] - mx) : 0.f;
            ss += a[mi];
        }
        ss = wsum(ss);
        float inv = 1.f / ss;
        float* ps = sm + OFF_P + warp * 128;
#pragma unroll
        for (int mi = 0; mi < 4; ++mi) {
            int m = lane + 32 * mi;
            if (m < NW) ps[m] = a[mi] * inv;
        }
        __syncwarp();
        float c0 = 0.f, c1 = 0.f;
#pragma unroll 4
        for (int m = 0; m < NW; ++m) {
            float pm = ps[m];
            c0 = fmaf(pm, sm[OFF_K + m * 65 + d0], c0);
            c1 = fmaf(pm, sm[OFF_K + m * 65 + d1], c1);
        }
        sm[OFF_X + r * DH + d0] = c0;
        sm[OFF_X + r * DH + d1] = c1;
        __syncwarp();
    }
    __syncthreads();

    // ================= Stage 3: QKV projection (q overwrites x row-wise) ===
    for (int idx = tid; idx < 192 * 64; idx += NTHR) {
        int e = idx >> 6, d = idx & 63;
        sm[OFF_W + d * 193 + e] = w_qkv[idx];   // wT[d][e]
    }
    __syncthreads();
    float bq[6];
#pragma unroll
    for (int k6 = 0; k6 < 6; ++k6) bq[k6] = b_qkv[lane + 32 * k6];
    for (int r = warp; r < NT; r += NWARP) {
        float* xs = sm + OFF_S + warp * 64;
        for (int j = lane; j < 64; j += 32) xs[j] = sm[OFF_X + r * DH + j];
        __syncwarp();
        float acc[6];
#pragma unroll
        for (int k6 = 0; k6 < 6; ++k6) acc[k6] = bq[k6];
#pragma unroll 4
        for (int d = 0; d < DH; ++d) {
            float xd = xs[d];
#pragma unroll
            for (int k6 = 0; k6 < 6; ++k6)
                acc[k6] = fmaf(xd, sm[OFF_W + d * 193 + lane + 32 * k6], acc[k6]);
        }
        sm[OFF_X + r * DH + lane]      = acc[0];
        sm[OFF_X + r * DH + lane + 32] = acc[1];
        sm[OFF_K + r * 65 + lane]      = acc[2];
        sm[OFF_K + r * 65 + lane + 32] = acc[3];
        sm[OFF_V + r * 65 + lane]      = acc[4];
        sm[OFF_V + r * 65 + lane + 32] = acc[5];
        __syncwarp();
    }
    __syncthreads();

    // ================= Stage 4: 4-head self-attention (o overwrites q) =====
    for (int r = warp; r < NT; r += NWARP) {
        float* qr = sm + OFF_X + r * DH;
        float* ps = sm + OFF_P + warp * 200;
        for (int h = 0; h < NH; ++h) {
            int koff[7];
#pragma unroll
            for (int j = 0; j < 7; ++j) {
                int m = lane + 32 * j;
                koff[j] = OFF_K + (m < NT ? m : NT - 1) * 65 + h * HD;
            }
            float a[7] = {0.f, 0.f, 0.f, 0.f, 0.f, 0.f, 0.f};
#pragma unroll
            for (int d = 0; d < HD; ++d) {
                float qd = qr[h * HD + d];
#pragma unroll
                for (int j = 0; j < 7; ++j) a[j] = fmaf(qd, sm[koff[j] + d], a[j]);
            }
            float mx = -1e30f;
#pragma unroll
            for (int j = 0; j < 7; ++j) {
                a[j] = (lane + 32 * j < NT) ? a[j] * 0.25f : -1e30f;
                mx = fmaxf(mx, a[j]);
            }
            mx = wmax(mx);
            float ss = 0.f;
#pragma unroll
            for (int j = 0; j < 7; ++j) {
                a[j] = (lane + 32 * j < NT) ? __expf(a[j] - mx) : 0.f;
                ss += a[j];
            }
            ss = wsum(ss);
            float inv = 1.f / ss;
#pragma unroll
            for (int j = 0; j < 7; ++j) {
                int m = lane + 32 * j;
                if (m < NT) ps[m] = a[j] * inv;
            }
            __syncwarp();
            // o[d] for this head's 16 dims; lanes split the m range in half
            const int dd = lane & 15;
            const int m0 = (lane >> 4) * 100;
            float oa = 0.f;
#pragma unroll 4
            for (int m = m0; m < m0 + 100; ++m)
                oa = fmaf(ps[m], sm[OFF_V + m * 65 + h * HD + dd], oa);
            oa += __shfl_xor_sync(0xffffffffu, oa, 16);
            __syncwarp();
            if (lane < 16) qr[h * HD + dd] = oa;  // q[h*16..] dead for this row
            __syncwarp();
        }
    }
    __syncthreads();

    // ================= Stage 5: attn_out -> out_proj + residual ============
    for (int idx = tid; idx < 64 * 64; idx += NTHR) {
        int e = idx >> 6, d = idx & 63;
        sm[OFF_AO + d * 65 + e] = w_ao[idx];       // aoT[d][e]
    }
    for (int idx = tid; idx < 256 * 64; idx += NTHR) {
        int c = idx >> 6, e = idx & 63;
        sm[OFF_OP + e * 257 + c] = w_op[idx];      // opT[e][c]
    }
    __syncthreads();
    const float bao0 = b_ao[d0], bao1 = b_ao[d1];
    float bop[8];
#pragma unroll
    for (int j = 0; j < 8; ++j) bop[j] = b_op[lane + 32 * j];
    for (int r = warp; r < NT; r += NWARP) {
        const float* orow = sm + OFF_X + r * DH;
        float a0 = bao0, a1 = bao1;
#pragma unroll 4
        for (int d = 0; d < DH; ++d) {
            float od = orow[d];
            a0 = fmaf(od, sm[OFF_AO + d * 65 + d0], a0);
            a1 = fmaf(od, sm[OFF_AO + d * 65 + d1], a1);
        }
        float* as = sm + OFF_S + warp * 64;
        as[d0] = a0; as[d1] = a1;
        __syncwarp();
        float acc[8];
#pragma unroll
        for (int j = 0; j < 8; ++j)
            acc[j] = bop[j] + turb_s[(size_t)r * CM + lane + 32 * j];
#pragma unroll 2
        for (int e = 0; e < DH; ++e) {
            float ae = as[e];
#pragma unroll
            for (int j = 0; j < 8; ++j)
                acc[j] = fmaf(ae, sm[OFF_OP + e * 257 + lane + 32 * j], acc[j]);
        }
#pragma unroll
        for (int j = 0; j < 8; ++j)
            out_s[(size_t)r * CM + lane + 32 * j] = acc[j];
        __syncwarp();
    }
}

extern "C" void kernel_launch(void* const* d_in, const int* in_sizes, int n_in,
                              void* d_out, int out_size)
{
    const float* turb  = (const float*)d_in[0];
    const float* weath = (const float*)d_in[1];
    const float* w_t   = (const float*)d_in[2];
    const float* b_t   = (const float*)d_in[3];
    const float* w_w   = (const float*)d_in[4];
    const float* b_w   = (const float*)d_in[5];
    const float* g_t   = (const float*)d_in[6];
    const float* be_t  = (const float*)d_in[7];
    const float* g_w   = (const float*)d_in[8];
    const float* be_w  = (const float*)d_in[9];
    const float* w_qkv = (const float*)d_in[10];
    const float* b_qkv = (const float*)d_in[11];
    const float* w_ao  = (const float*)d_in[12];
    const float* b_ao  = (const float*)d_in[13];
    const float* w_op  = (const float*)d_in[14];
    const float* b_op  = (const float*)d_in[15];
    float* out = (float*)d_out;

    const int S = in_sizes[0] / (NT * CM);   // 768
    const size_t smem = (size_t)SMEM_F * sizeof(float);
    cudaFuncSetAttribute(wda_kernel, cudaFuncAttributeMaxDynamicSharedMemorySize,
                         (int)smem);
    wda_kernel<<<S, NTHR, smem>>>(turb, weath, w_t, b_t, w_w, b_w,
                                  g_t, be_t, g_w, be_w, w_qkv, b_qkv,
                                  w_ao, b_ao, w_op, b_op, out);
}

// round 3
// speedup vs baseline: 1.9838x; 1.9838x over previous
#include <cuda_runtime.h>

// WeatherDifferentiatedAttention — fused, one CTA per (b,t) sequence.
// Round 3 (= Round 2 design, macro fix): register-tiled, float4-vectorized
// smem access. Warp computes a 4-row tile; lane = (h, et): h in {0,1} picks
// 2 rows, et in [0,16) picks 4 output cols. x-loads broadcast across et
// (1 wavefront), weight float4 loads use 4*odd strides (68/196/260).

constexpr int NTHR = 512;
constexpr int NWARP = 16;
constexpr int NT = 200, NW = 100, CM = 256;

// smem float offsets
constexpr int OFF_X = 0;                   // [200][64]  x / q / o
constexpr int OFF_K = 12800;               // [208][68]  h_w / k  (stage5: opT)
constexpr int OFF_V = OFF_K + 208 * 68;    // [208][68]  h_t / v
constexpr int OFF_W = OFF_V + 208 * 68;    // 13312: weights / probs / A-buf
constexpr int SMEM_F = OFF_W + 13312;      // 54400 floats = 217600 B

__device__ __forceinline__ float4 ld4(const float* p) {
    return *reinterpret_cast<const float4*>(p);
}
__device__ __forceinline__ void st4(float* p, const float4 v) {
    *reinterpret_cast<float4*>(p) = v;
}
__device__ __forceinline__ float hsum16(float v) {
    v += __shfl_xor_sync(0xffffffffu, v, 1);
    v += __shfl_xor_sync(0xffffffffu, v, 2);
    v += __shfl_xor_sync(0xffffffffu, v, 4);
    v += __shfl_xor_sync(0xffffffffu, v, 8);
    return v;
}
__device__ __forceinline__ float hmax16(float v) {
    v = fmaxf(v, __shfl_xor_sync(0xffffffffu, v, 1));
    v = fmaxf(v, __shfl_xor_sync(0xffffffffu, v, 2));
    v = fmaxf(v, __shfl_xor_sync(0xffffffffu, v, 4));
    v = fmaxf(v, __shfl_xor_sync(0xffffffffu, v, 8));
    return v;
}
__device__ __forceinline__ float dot4(const float4 a, const float4 b, float acc) {
    return fmaf(a.x, b.x, fmaf(a.y, b.y, fmaf(a.z, b.z, fmaf(a.w, b.w, acc))));
}
// NOTE: parameter must not be named 'w' (would capture the '.w' field access)
#define FMA4(acc, xs, wv) { (acc).x = fmaf((xs),(wv).x,(acc).x); \
                            (acc).y = fmaf((xs),(wv).y,(acc).y); \
                            (acc).z = fmaf((xs),(wv).z,(acc).z); \
                            (acc).w = fmaf((xs),(wv).w,(acc).w); }

__global__ __launch_bounds__(NTHR, 1) void wda_kernel(
    const float* __restrict__ turb, const float* __restrict__ weath,
    const float* __restrict__ w_t,  const float* __restrict__ b_t,
    const float* __restrict__ w_w,  const float* __restrict__ b_w,
    const float* __restrict__ g_t,  const float* __restrict__ be_t,
    const float* __restrict__ g_w,  const float* __restrict__ be_w,
    const float* __restrict__ w_qkv,const float* __restrict__ b_qkv,
    const float* __restrict__ w_ao, const float* __restrict__ b_ao,
    const float* __restrict__ w_op, const float* __restrict__ b_op,
    float* __restrict__ out)
{
    extern __shared__ float sm[];
    const int tid  = threadIdx.x;
    const int warp = tid >> 5, lane = tid & 31;
    const int hh2  = (lane >> 4) * 2;     // row offset within 4-row group
    const int et   = lane & 15;
    const int e4   = et * 4;
    const size_t s = blockIdx.x;
    const float* turb_s  = turb  + s * (size_t)(NT * CM);
    const float* weath_s = weath + s * (size_t)(NW * CM);
    float*       out_s   = out   + s * (size_t)(NT * CM);

    // zero V pad rows 200..207 (stage-4 context over-reads with p=0)
    for (int i = tid; i < 8 * 68; i += NTHR) sm[OFF_V + 200 * 68 + i] = 0.f;

    // ============ Stage 1: h = LN(x @ W^T + b) for turbine & weather ======
#pragma unroll 1
    for (int src = 0; src < 2; ++src) {
        const float* inp = src ? weath_s : turb_s;
        const float* Wg  = src ? w_w  : w_t;
        const float* bg  = src ? b_w  : b_t;
        const float* gg  = src ? g_w  : g_t;
        const float* beg = src ? be_w : be_t;
        const int ngrp   = (src ? NW : NT) >> 2;
        float* hb = sm + (src ? OFF_K : OFF_V);
        const float4 bv = ld4(bg + e4), gv = ld4(gg + e4), ev = ld4(beg + e4);

#pragma unroll 1
        for (int ch = 0; ch < 2; ++ch) {
            __syncthreads();
            // stage wT chunk [128][68]: sm[c*68+d] = Wg[d*256 + ch*128 + c]
            for (int idx = tid; idx < 64 * 128; idx += NTHR) {
                const int d = idx >> 7, c = idx & 127;
                sm[OFF_W + c * 68 + d] = Wg[d * 256 + ch * 128 + c];
            }
            __syncthreads();
#pragma unroll 1
            for (int g = warp; g < ngrp; g += NWARP) {
                const int rA = g * 4 + hh2;
                const float* xA = inp + (size_t)rA * CM + ch * 128;
                const float* xB = xA + CM;
                float4 accA = {0,0,0,0}, accB = {0,0,0,0};
#pragma unroll 4
                for (int k = 0; k < 128; k += 4) {
                    const float4 a = ld4(xA + k), b = ld4(xB + k);
                    const float* wp = sm + OFF_W + k * 68 + e4;
                    const float4 w0 = ld4(wp),       w1 = ld4(wp + 68),
                                 w2 = ld4(wp + 136), w3 = ld4(wp + 204);
                    FMA4(accA, a.x, w0); FMA4(accA, a.y, w1);
                    FMA4(accA, a.z, w2); FMA4(accA, a.w, w3);
                    FMA4(accB, b.x, w0); FMA4(accB, b.y, w1);
                    FMA4(accB, b.z, w2); FMA4(accB, b.w, w3);
                }
                float* hA = hb + rA * 68 + e4;
                float* hB = hA + 68;
                if (ch == 0) { st4(hA, accA); st4(hB, accB); }
                else {
                    const float4 pA = ld4(hA), pB = ld4(hB);
                    float4 yA = { accA.x+pA.x+bv.x, accA.y+pA.y+bv.y,
                                  accA.z+pA.z+bv.z, accA.w+pA.w+bv.w };
                    float4 yB = { accB.x+pB.x+bv.x, accB.y+pB.y+bv.y,
                                  accB.z+pB.z+bv.z, accB.w+pB.w+bv.w };
                    const float muA = hsum16(yA.x+yA.y+yA.z+yA.w) * 0.015625f;
                    const float qA  = hsum16(yA.x*yA.x+yA.y*yA.y+yA.z*yA.z+yA.w*yA.w) * 0.015625f;
                    const float rsA = rsqrtf(qA - muA*muA + 1e-5f);
                    const float muB = hsum16(yB.x+yB.y+yB.z+yB.w) * 0.015625f;
                    const float qB  = hsum16(yB.x*yB.x+yB.y*yB.y+yB.z*yB.z+yB.w*yB.w) * 0.015625f;
                    const float rsB = rsqrtf(qB - muB*muB + 1e-5f);
                    yA.x = (yA.x-muA)*rsA*gv.x + ev.x;
                    yA.y = (yA.y-muA)*rsA*gv.y + ev.y;
                    yA.z = (yA.z-muA)*rsA*gv.z + ev.z;
                    yA.w = (yA.w-muA)*rsA*gv.w + ev.w;
                    yB.x = (yB.x-muB)*rsB*gv.x + ev.x;
                    yB.y = (yB.y-muB)*rsB*gv.y + ev.y;
                    yB.z = (yB.z-muB)*rsB*gv.z + ev.z;
                    yB.w = (yB.w-muB)*rsB*gv.w + ev.w;
                    st4(hA, yA); st4(hB, yB);
                }
            }
        }
    }
    __syncthreads();

    // ============ Stage 2: cross-attention, x = softmax(h_t h_w^T/8) h_w ==
    {
        float* P  = sm + OFF_W + warp * 832;
        float* pA = P + hh2 * 112;
        float* pB = pA + 112;
#pragma unroll 1
        for (int g = warp; g < NT / 4; g += NWARP) {
            const int rA = g * 4 + hh2;
            const float* qA = sm + OFF_V + rA * 68;
            const float* qB = qA + 68;
            float lA[7], lB[7];
#pragma unroll
            for (int j = 0; j < 7; ++j) { lA[j] = 0.f; lB[j] = 0.f; }
#pragma unroll
            for (int d = 0; d < 64; d += 4) {
                const float4 a = ld4(qA + d), b = ld4(qB + d);
#pragma unroll
                for (int j = 0; j < 7; ++j) {
                    const float4 kv = ld4(sm + OFF_K + (et + 16*j) * 68 + d);
                    lA[j] = dot4(a, kv, lA[j]);
                    lB[j] = dot4(b, kv, lB[j]);
                }
            }
            float mA = -1e30f, mB = -1e30f;
#pragma unroll
            for (int j = 0; j < 7; ++j) {
                const bool ok = et + 16*j < NW;
                lA[j] = ok ? lA[j] * 0.125f : -1e30f;
                lB[j] = ok ? lB[j] * 0.125f : -1e30f;
                mA = fmaxf(mA, lA[j]); mB = fmaxf(mB, lB[j]);
            }
            mA = hmax16(mA); mB = hmax16(mB);
            float sA = 0.f, sB = 0.f;
#pragma unroll
            for (int j = 0; j < 7; ++j) {
                const bool ok = et + 16*j < NW;
                lA[j] = ok ? __expf(lA[j] - mA) : 0.f;
                lB[j] = ok ? __expf(lB[j] - mB) : 0.f;
                sA += lA[j]; sB += lB[j];
            }
            const float iA = 1.f / hsum16(sA), iB = 1.f / hsum16(sB);
#pragma unroll
            for (int j = 0; j < 7; ++j) {
                const int m = et + 16*j;
                if (m < NW) { pA[m] = lA[j] * iA; pB[m] = lB[j] * iB; }
            }
            __syncwarp();
            float4 cA = {0,0,0,0}, cB = {0,0,0,0};
#pragma unroll 5
            for (int m = 0; m < NW; m += 4) {
                const float4 pa = ld4(pA + m), pb = ld4(pB + m);
                const float* kp = sm + OFF_K + m * 68 + e4;
                const float4 k0 = ld4(kp),       k1 = ld4(kp + 68),
                             k2 = ld4(kp + 136), k3 = ld4(kp + 204);
                FMA4(cA, pa.x, k0); FMA4(cA, pa.y, k1);
                FMA4(cA, pa.z, k2); FMA4(cA, pa.w, k3);
                FMA4(cB, pb.x, k0); FMA4(cB, pb.y, k1);
                FMA4(cB, pb.z, k2); FMA4(cB, pb.w, k3);
            }
            st4(sm + OFF_X + rA * 64 + e4, cA);
            st4(sm + OFF_X + (rA+1) * 64 + e4, cB);
            __syncwarp();
        }
    }
    __syncthreads();

    // ============ Stage 3: QKV projection ==================================
    for (int idx = tid; idx < 192 * 64; idx += NTHR) {
        const int e = idx >> 6, d = idx & 63;
        sm[OFF_W + d * 196 + e] = w_qkv[idx];     // wT[d][e], stride 196
    }
    __syncthreads();
    {
        const float4 bq0 = ld4(b_qkv + e4), bq1 = ld4(b_qkv + 64 + e4),
                     bq2 = ld4(b_qkv + 128 + e4);
#pragma unroll 1
        for (int g = warp; g < NT / 4; g += NWARP) {
            const int rA = g * 4 + hh2;
            const float* xA = sm + OFF_X + rA * 64;
            const float* xB = xA + 64;
            float4 qA = bq0, kA = bq1, vA = bq2;
            float4 qB = bq0, kB = bq1, vB = bq2;
#pragma unroll 4
            for (int d = 0; d < 64; d += 4) {
                const float4 a = ld4(xA + d), b = ld4(xB + d);
#define QKV_STEP(xa, xb, dd) { \
                const float* wp = sm + OFF_W + (d + dd) * 196 + e4; \
                const float4 w0 = ld4(wp), w1 = ld4(wp + 64), w2 = ld4(wp + 128); \
                FMA4(qA, xa, w0); FMA4(kA, xa, w1); FMA4(vA, xa, w2); \
                FMA4(qB, xb, w0); FMA4(kB, xb, w1); FMA4(vB, xb, w2); }
                QKV_STEP(a.x, b.x, 0) QKV_STEP(a.y, b.y, 1)
                QKV_STEP(a.z, b.z, 2) QKV_STEP(a.w, b.w, 3)
#undef QKV_STEP
            }
            st4(sm + OFF_X + rA * 64 + e4, qA);       // q overwrites x
            st4(sm + OFF_X + (rA+1) * 64 + e4, qB);
            st4(sm + OFF_K + rA * 68 + e4, kA);
            st4(sm + OFF_K + (rA+1) * 68 + e4, kB);
            st4(sm + OFF_V + rA * 68 + e4, vA);
            st4(sm + OFF_V + (rA+1) * 68 + e4, vB);
        }
    }
    __syncthreads();

    // ============ Stage 4: 4-head self-attention (o overwrites q) ==========
    {
        float* P  = sm + OFF_W + warp * 832;          // [4][208]
        float* pA = P + hh2 * 208;
        float* pB = pA + 208;
        const int ms = et >> 2, dd4 = (et & 3) * 4;
#pragma unroll 1
        for (int g = warp; g < NT / 4; g += NWARP) {
            const int rA = g * 4 + hh2;
            if (et < 8) { pA[200 + et] = 0.f; pB[200 + et] = 0.f; }
#pragma unroll 1
            for (int hd0 = 0; hd0 < 64; hd0 += 16) {
                const float* qA = sm + OFF_X + rA * 64 + hd0;
                const float* qB = qA + 64;
                float lA[13], lB[13];
#pragma unroll
                for (int j = 0; j < 13; ++j) { lA[j] = 0.f; lB[j] = 0.f; }
#pragma unroll
                for (int d = 0; d < 16; d += 4) {
                    const float4 a = ld4(qA + d), b = ld4(qB + d);
#pragma unroll
                    for (int j = 0; j < 13; ++j) {
                        const float4 kv = ld4(sm + OFF_K + (et + 16*j) * 68 + hd0 + d);
                        lA[j] = dot4(a, kv, lA[j]);
                        lB[j] = dot4(b, kv, lB[j]);
                    }
                }
                float mA = -1e30f, mB = -1e30f;
#pragma unroll
                for (int j = 0; j < 13; ++j) {
                    const bool ok = et + 16*j < NT;
                    lA[j] = ok ? lA[j] * 0.25f : -1e30f;
                    lB[j] = ok ? lB[j] * 0.25f : -1e30f;
                    mA = fmaxf(mA, lA[j]); mB = fmaxf(mB, lB[j]);
                }
                mA = hmax16(mA); mB = hmax16(mB);
                float sA = 0.f, sB = 0.f;
#pragma unroll
                for (int j = 0; j < 13; ++j) {
                    const bool ok = et + 16*j < NT;
                    lA[j] = ok ? __expf(lA[j] - mA) : 0.f;
                    lB[j] = ok ? __expf(lB[j] - mB) : 0.f;
                    sA += lA[j]; sB += lB[j];
                }
                const float iA = 1.f / hsum16(sA), iB = 1.f / hsum16(sB);
#pragma unroll
                for (int j = 0; j < 13; ++j) {
                    const int m = et + 16*j;
                    if (m < NT) { pA[m] = lA[j] * iA; pB[m] = lB[j] * iB; }
                }
                __syncwarp();
                float4 oA = {0,0,0,0}, oB = {0,0,0,0};
                const int m0 = ms * 52;
#pragma unroll
                for (int mi = 0; mi < 52; mi += 4) {
                    const int m = m0 + mi;
                    const float4 pa = ld4(pA + m), pb = ld4(pB + m);
                    const float* vp = sm + OFF_V + m * 68 + hd0 + dd4;
                    const float4 v0 = ld4(vp),       v1 = ld4(vp + 68),
                                 v2 = ld4(vp + 136), v3 = ld4(vp + 204);
                    FMA4(oA, pa.x, v0); FMA4(oA, pa.y, v1);
                    FMA4(oA, pa.z, v2); FMA4(oA, pa.w, v3);
                    FMA4(oB, pb.x, v0); FMA4(oB, pb.y, v1);
                    FMA4(oB, pb.z, v2); FMA4(oB, pb.w, v3);
                }
#define RED48(c) { c += __shfl_xor_sync(0xffffffffu, c, 4); \
                   c += __shfl_xor_sync(0xffffffffu, c, 8); }
                RED48(oA.x) RED48(oA.y) RED48(oA.z) RED48(oA.w)
                RED48(oB.x) RED48(oB.y) RED48(oB.z) RED48(oB.w)
#undef RED48
                if (ms == 0) {
                    st4(sm + OFF_X + rA * 64 + hd0 + dd4, oA);
                    st4(sm + OFF_X + (rA+1) * 64 + hd0 + dd4, oB);
                }
                __syncwarp();
            }
        }
    }
    __syncthreads();

    // ============ Stage 5: attn_out -> out_proj + residual =================
    for (int idx = tid; idx < 64 * 64; idx += NTHR) {
        const int e = idx >> 6, d = idx & 63;
        sm[OFF_W + d * 68 + e] = w_ao[idx];           // aoT[d][e], stride 68
    }
    for (int idx = tid; idx < 256 * 64; idx += NTHR) {
        const int c = idx >> 6, e = idx & 63;
        sm[OFF_K + e * 260 + c] = w_op[idx];          // opT[e][c], stride 260
    }
    __syncthreads();
    {
        const float4 bao  = ld4(b_ao + e4);
        const float4 bop0 = ld4(b_op + e4),       bop1 = ld4(b_op + 64 + e4),
                     bop2 = ld4(b_op + 128 + e4), bop3 = ld4(b_op + 192 + e4);
        float* Abuf = sm + OFF_W + 4352 + warp * 288;
#pragma unroll 1
        for (int g = warp; g < NT / 4; g += NWARP) {
            const int rA = g * 4 + hh2;
            const float* oA = sm + OFF_X + rA * 64;
            const float* oB = oA + 64;
            float4 aA = bao, aB = bao;
#pragma unroll 4
            for (int d = 0; d < 64; d += 4) {
                const float4 a = ld4(oA + d), b = ld4(oB + d);
                const float* wp = sm + OFF_W + d * 68 + e4;
                const float4 w0 = ld4(wp),       w1 = ld4(wp + 68),
                             w2 = ld4(wp + 136), w3 = ld4(wp + 204);
                FMA4(aA, a.x, w0); FMA4(aA, a.y, w1);
                FMA4(aA, a.z, w2); FMA4(aA, a.w, w3);
                FMA4(aB, b.x, w0); FMA4(aB, b.y, w1);
                FMA4(aB, b.z, w2); FMA4(aB, b.w, w3);
            }
            st4(Abuf + hh2 * 68 + e4, aA);
            st4(Abuf + hh2 * 68 + 68 + e4, aB);
            __syncwarp();
            const float* tA = turb_s + (size_t)rA * CM;
            const float* tB = tA + CM;
            float* outA = out_s + (size_t)rA * CM;
            float* outB = outA + CM;
            float4 accA[4], accB[4];
            {
                float4 r;
                r = ld4(tA + e4);       accA[0] = make_float4(bop0.x+r.x, bop0.y+r.y, bop0.z+r.z, bop0.w+r.w);
                r = ld4(tA + 64 + e4);  accA[1] = make_float4(bop1.x+r.x, bop1.y+r.y, bop1.z+r.z, bop1.w+r.w);
                r = ld4(tA + 128 + e4); accA[2] = make_float4(bop2.x+r.x, bop2.y+r.y, bop2.z+r.z, bop2.w+r.w);
                r = ld4(tA + 192 + e4); accA[3] = make_float4(bop3.x+r.x, bop3.y+r.y, bop3.z+r.z, bop3.w+r.w);
                r = ld4(tB + e4);       accB[0] = make_float4(bop0.x+r.x, bop0.y+r.y, bop0.z+r.z, bop0.w+r.w);
                r = ld4(tB + 64 + e4);  accB[1] = make_float4(bop1.x+r.x, bop1.y+r.y, bop1.z+r.z, bop1.w+r.w);
                r = ld4(tB + 128 + e4); accB[2] = make_float4(bop2.x+r.x, bop2.y+r.y, bop2.z+r.z, bop2.w+r.w);
                r = ld4(tB + 192 + e4); accB[3] = make_float4(bop3.x+r.x, bop3.y+r.y, bop3.z+r.z, bop3.w+r.w);
            }
            const float* arowA = Abuf + hh2 * 68;
            const float* arowB = arowA + 68;
#pragma unroll 2
            for (int e = 0; e < 64; e += 4) {
                const float4 a = ld4(arowA + e), b = ld4(arowB + e);
#define OP_STEP(xa, xb, ee) { \
                const float* wp = sm + OFF_K + (e + ee) * 260 + e4; \
                const float4 w0 = ld4(wp),       w1 = ld4(wp + 64), \
                             w2 = ld4(wp + 128), w3 = ld4(wp + 192); \
                FMA4(accA[0], xa, w0); FMA4(accA[1], xa, w1); \
                FMA4(accA[2], xa, w2); FMA4(accA[3], xa, w3); \
                FMA4(accB[0], xb, w0); FMA4(accB[1], xb, w1); \
                FMA4(accB[2], xb, w2); FMA4(accB[3], xb, w3); }
                OP_STEP(a.x, b.x, 0) OP_STEP(a.y, b.y, 1)
                OP_STEP(a.z, b.z, 2) OP_STEP(a.w, b.w, 3)
#undef OP_STEP
            }
            st4(outA + e4,       accA[0]); st4(outA + 64 + e4,  accA[1]);
            st4(outA + 128 + e4, accA[2]); st4(outA + 192 + e4, accA[3]);
            st4(outB + e4,       accB[0]); st4(outB + 64 + e4,  accB[1]);
            st4(outB + 128 + e4, accB[2]); st4(outB + 192 + e4, accB[3]);
            __syncwarp();
        }
    }
}

extern "C" void kernel_launch(void* const* d_in, const int* in_sizes, int n_in,
                              void* d_out, int out_size)
{
    const float* turb  = (const float*)d_in[0];
    const float* weath = (const float*)d_in[1];
    const float* w_t   = (const float*)d_in[2];
    const float* b_t   = (const float*)d_in[3];
    const float* w_w   = (const float*)d_in[4];
    const float* b_w   = (const float*)d_in[5];
    const float* g_t   = (const float*)d_in[6];
    const float* be_t  = (const float*)d_in[7];
    const float* g_w   = (const float*)d_in[8];
    const float* be_w  = (const float*)d_in[9];
    const float* w_qkv = (const float*)d_in[10];
    const float* b_qkv = (const float*)d_in[11];
    const float* w_ao  = (const float*)d_in[12];
    const float* b_ao  = (const float*)d_in[13];
    const float* w_op  = (const float*)d_in[14];
    const float* b_op  = (const float*)d_in[15];
    float* out = (float*)d_out;

    const int S = in_sizes[0] / (NT * CM);   // 768
    const size_t smem = (size_t)SMEM_F * sizeof(float);
    cudaFuncSetAttribute(wda_kernel, cudaFuncAttributeMaxDynamicSharedMemorySize,
                         (int)smem);
    wda_kernel<<<S, NTHR, smem>>>(turb, weath, w_t, b_t, w_w, b_w,
                                  g_t, be_t, g_w, be_w, w_qkv, b_qkv,
                                  w_ao, b_ao, w_op, b_op, out);
}

// round 4
// speedup vs baseline: 2.1246x; 1.0710x over previous
#include <cuda_runtime.h>

// WeatherDifferentiatedAttention — fused, one CTA per (b,t) sequence.
// Round 4: f32x2 packed FMA (FFMA2) in all broadcast-GEMM loops + 8-row
// register tiles in stage 1. Lane = (h, et) as before.

constexpr int NTHR = 512;
constexpr int NWARP = 16;
constexpr int NT = 200, NW = 100, CM = 256;

// smem float offsets
constexpr int OFF_X = 0;                   // [200][64]  x / q / o
constexpr int OFF_K = 12800;               // [208][68]  h_w / k  (stage5: opT)
constexpr int OFF_V = OFF_K + 208 * 68;    // [208][68]  h_t / v
constexpr int OFF_W = OFF_V + 208 * 68;    // 13312: weights / probs / A-buf
constexpr int SMEM_F = OFF_W + 13312;      // 54400 floats = 217600 B

typedef unsigned long long u64;

__device__ __forceinline__ float4 ld4(const float* p) {
    return *reinterpret_cast<const float4*>(p);
}
__device__ __forceinline__ void st4(float* p, const float4 v) {
    *reinterpret_cast<float4*>(p) = v;
}
__device__ __forceinline__ ulonglong2 ld4u(const float* p) {
    return *reinterpret_cast<const ulonglong2*>(p);
}
__device__ __forceinline__ void st4u(float* p, const u64 lo, const u64 hi) {
    *reinterpret_cast<ulonglong2*>(p) = make_ulonglong2(lo, hi);
}
// pack scalar into both f32x2 lanes
__device__ __forceinline__ u64 pk1(float s) {
    u64 r; unsigned u = __float_as_uint(s);
    asm("mov.b64 %0, {%1, %1};" : "=l"(r) : "r"(u));
    return r;
}
__device__ __forceinline__ u64 pk2(float lo, float hi) {
    u64 r;
    asm("mov.b64 %0, {%1, %2};" : "=l"(r)
        : "r"(__float_as_uint(lo)), "r"(__float_as_uint(hi)));
    return r;
}
__device__ __forceinline__ void upk(u64 v, float& lo, float& hi) {
    unsigned a, b;
    asm("mov.b64 {%0, %1}, %2;" : "=r"(a), "=r"(b) : "l"(v));
    lo = __uint_as_float(a); hi = __uint_as_float(b);
}
// acc (f32x2) += s2 * wv  (elementwise packed fp32 FMA)
#define FMA2(acc, s2, wv) \
    asm("fma.rn.f32x2 %0, %1, %2, %0;" : "+l"(acc) : "l"(s2), "l"(wv))
#define FMA4P(a0, a1, s2, wv) { u64 _s = (s2); FMA2(a0, _s, (wv).x); FMA2(a1, _s, (wv).y); }

__device__ __forceinline__ float hsum16(float v) {
    v += __shfl_xor_sync(0xffffffffu, v, 1);
    v += __shfl_xor_sync(0xffffffffu, v, 2);
    v += __shfl_xor_sync(0xffffffffu, v, 4);
    v += __shfl_xor_sync(0xffffffffu, v, 8);
    return v;
}
__device__ __forceinline__ float hmax16(float v) {
    v = fmaxf(v, __shfl_xor_sync(0xffffffffu, v, 1));
    v = fmaxf(v, __shfl_xor_sync(0xffffffffu, v, 2));
    v = fmaxf(v, __shfl_xor_sync(0xffffffffu, v, 4));
    v = fmaxf(v, __shfl_xor_sync(0xffffffffu, v, 8));
    return v;
}
__device__ __forceinline__ float dot4(const float4 a, const float4 b, float acc) {
    return fmaf(a.x, b.x, fmaf(a.y, b.y, fmaf(a.z, b.z, fmaf(a.w, b.w, acc))));
}

__global__ __launch_bounds__(NTHR, 1) void wda_kernel(
    const float* __restrict__ turb, const float* __restrict__ weath,
    const float* __restrict__ w_t,  const float* __restrict__ b_t,
    const float* __restrict__ w_w,  const float* __restrict__ b_w,
    const float* __restrict__ g_t,  const float* __restrict__ be_t,
    const float* __restrict__ g_w,  const float* __restrict__ be_w,
    const float* __restrict__ w_qkv,const float* __restrict__ b_qkv,
    const float* __restrict__ w_ao, const float* __restrict__ b_ao,
    const float* __restrict__ w_op, const float* __restrict__ b_op,
    float* __restrict__ out)
{
    extern __shared__ float sm[];
    const int tid  = threadIdx.x;
    const int warp = tid >> 5, lane = tid & 31;
    const int hh   = lane >> 4;           // half-warp id
    const int hh2  = hh * 2;
    const int et   = lane & 15;
    const int e4   = et * 4;
    const size_t s = blockIdx.x;
    const float* turb_s  = turb  + s * (size_t)(NT * CM);
    const float* weath_s = weath + s * (size_t)(NW * CM);
    float*       out_s   = out   + s * (size_t)(NT * CM);

    // zero V pad rows 200..207 (stage-4 context over-reads with p=0)
    for (int i = tid; i < 8 * 68; i += NTHR) sm[OFF_V + 200 * 68 + i] = 0.f;

    // ============ Stage 1: h = LN(x @ W^T + b), 8-row tiles per warp ======
#pragma unroll 1
    for (int src = 0; src < 2; ++src) {
        const float* inp = src ? weath_s : turb_s;
        const float* Wg  = src ? w_w  : w_t;
        const float* bg  = src ? b_w  : b_t;
        const float* gg  = src ? g_w  : g_t;
        const float* beg = src ? be_w : be_t;
        const int ngrp   = src ? 13 : 25;         // 8-row groups (weather padded)
        const int rmax   = src ? NW - 1 : NT - 1;
        float* hb = sm + (src ? OFF_K : OFF_V);
        const float4 bv = ld4(bg + e4), gv = ld4(gg + e4), ev = ld4(beg + e4);

#pragma unroll 1
        for (int ch = 0; ch < 2; ++ch) {
            __syncthreads();
            // stage wT chunk [128][68]: sm[c*68+d] = Wg[d*256 + ch*128 + c]
            for (int idx = tid; idx < 64 * 128; idx += NTHR) {
                const int d = idx >> 7, c = idx & 127;
                sm[OFF_W + c * 68 + d] = Wg[d * 256 + ch * 128 + c];
            }
            __syncthreads();
#pragma unroll 1
            for (int g = warp; g < ngrp; g += NWARP) {
                const int r0 = g * 8 + hh * 4;
                const float* xp0 = inp + (size_t)min(r0 + 0, rmax) * CM + ch * 128;
                const float* xp1 = inp + (size_t)min(r0 + 1, rmax) * CM + ch * 128;
                const float* xp2 = inp + (size_t)min(r0 + 2, rmax) * CM + ch * 128;
                const float* xp3 = inp + (size_t)min(r0 + 3, rmax) * CM + ch * 128;
                u64 ac[4][2] = {{0,0},{0,0},{0,0},{0,0}};
#pragma unroll 2
                for (int k = 0; k < 128; k += 4) {
                    const float4 x0 = ld4(xp0 + k), x1 = ld4(xp1 + k);
                    const float4 x2 = ld4(xp2 + k), x3 = ld4(xp3 + k);
                    const float* wp = sm + OFF_W + k * 68 + e4;
                    const ulonglong2 w0 = ld4u(wp),       w1 = ld4u(wp + 68),
                                     w2 = ld4u(wp + 136), w3 = ld4u(wp + 204);
                    FMA4P(ac[0][0], ac[0][1], pk1(x0.x), w0);
                    FMA4P(ac[0][0], ac[0][1], pk1(x0.y), w1);
                    FMA4P(ac[0][0], ac[0][1], pk1(x0.z), w2);
                    FMA4P(ac[0][0], ac[0][1], pk1(x0.w), w3);
                    FMA4P(ac[1][0], ac[1][1], pk1(x1.x), w0);
                    FMA4P(ac[1][0], ac[1][1], pk1(x1.y), w1);
                    FMA4P(ac[1][0], ac[1][1], pk1(x1.z), w2);
                    FMA4P(ac[1][0], ac[1][1], pk1(x1.w), w3);
                    FMA4P(ac[2][0], ac[2][1], pk1(x2.x), w0);
                    FMA4P(ac[2][0], ac[2][1], pk1(x2.y), w1);
                    FMA4P(ac[2][0], ac[2][1], pk1(x2.z), w2);
                    FMA4P(ac[2][0], ac[2][1], pk1(x2.w), w3);
                    FMA4P(ac[3][0], ac[3][1], pk1(x3.x), w0);
                    FMA4P(ac[3][0], ac[3][1], pk1(x3.y), w1);
                    FMA4P(ac[3][0], ac[3][1], pk1(x3.z), w2);
                    FMA4P(ac[3][0], ac[3][1], pk1(x3.w), w3);
                }
                if (ch == 0) {
#pragma unroll
                    for (int i = 0; i < 4; ++i)
                        st4u(hb + (r0 + i) * 68 + e4, ac[i][0], ac[i][1]);
                } else {
#pragma unroll
                    for (int i = 0; i < 4; ++i) {
                        float f0, f1, f2, f3;
                        upk(ac[i][0], f0, f1); upk(ac[i][1], f2, f3);
                        float* hr = hb + (r0 + i) * 68 + e4;
                        const float4 pv = ld4(hr);
                        float y0 = f0 + pv.x + bv.x, y1 = f1 + pv.y + bv.y;
                        float y2 = f2 + pv.z + bv.z, y3 = f3 + pv.w + bv.w;
                        const float mu = hsum16(y0 + y1 + y2 + y3) * 0.015625f;
                        const float qq = hsum16(y0*y0 + y1*y1 + y2*y2 + y3*y3) * 0.015625f;
                        const float rs = rsqrtf(qq - mu * mu + 1e-5f);
                        y0 = (y0 - mu) * rs * gv.x + ev.x;
                        y1 = (y1 - mu) * rs * gv.y + ev.y;
                        y2 = (y2 - mu) * rs * gv.z + ev.z;
                        y3 = (y3 - mu) * rs * gv.w + ev.w;
                        st4(hr, make_float4(y0, y1, y2, y3));
                    }
                }
            }
        }
    }
    __syncthreads();

    // ============ Stage 2: cross-attention, x = softmax(h_t h_w^T/8) h_w ==
    {
        float* P  = sm + OFF_W + warp * 832;
        float* pA = P + hh2 * 112;
        float* pB = pA + 112;
#pragma unroll 1
        for (int g = warp; g < NT / 4; g += NWARP) {
            const int rA = g * 4 + hh2;
            const float* qA = sm + OFF_V + rA * 68;
            const float* qB = qA + 68;
            float lA[7], lB[7];
#pragma unroll
            for (int j = 0; j < 7; ++j) { lA[j] = 0.f; lB[j] = 0.f; }
#pragma unroll
            for (int d = 0; d < 64; d += 4) {
                const float4 a = ld4(qA + d), b = ld4(qB + d);
#pragma unroll
                for (int j = 0; j < 7; ++j) {
                    const float4 kv = ld4(sm + OFF_K + (et + 16*j) * 68 + d);
                    lA[j] = dot4(a, kv, lA[j]);
                    lB[j] = dot4(b, kv, lB[j]);
                }
            }
            float mA = -1e30f, mB = -1e30f;
#pragma unroll
            for (int j = 0; j < 7; ++j) {
                const bool ok = et + 16*j < NW;
                lA[j] = ok ? lA[j] * 0.125f : -1e30f;
                lB[j] = ok ? lB[j] * 0.125f : -1e30f;
                mA = fmaxf(mA, lA[j]); mB = fmaxf(mB, lB[j]);
            }
            mA = hmax16(mA); mB = hmax16(mB);
            float sA = 0.f, sB = 0.f;
#pragma unroll
            for (int j = 0; j < 7; ++j) {
                const bool ok = et + 16*j < NW;
                lA[j] = ok ? __expf(lA[j] - mA) : 0.f;
                lB[j] = ok ? __expf(lB[j] - mB) : 0.f;
                sA += lA[j]; sB += lB[j];
            }
            const float iA = 1.f / hsum16(sA), iB = 1.f / hsum16(sB);
#pragma unroll
            for (int j = 0; j < 7; ++j) {
                const int m = et + 16*j;
                if (m < NW) { pA[m] = lA[j] * iA; pB[m] = lB[j] * iB; }
            }
            __syncwarp();
            u64 c0A = 0, c1A = 0, c0B = 0, c1B = 0;
#pragma unroll 5
            for (int m = 0; m < NW; m += 4) {
                const float4 pa = ld4(pA + m), pb = ld4(pB + m);
                const float* kp = sm + OFF_K + m * 68 + e4;
                const ulonglong2 k0 = ld4u(kp),       k1 = ld4u(kp + 68),
                                 k2 = ld4u(kp + 136), k3 = ld4u(kp + 204);
                FMA4P(c0A, c1A, pk1(pa.x), k0); FMA4P(c0A, c1A, pk1(pa.y), k1);
                FMA4P(c0A, c1A, pk1(pa.z), k2); FMA4P(c0A, c1A, pk1(pa.w), k3);
                FMA4P(c0B, c1B, pk1(pb.x), k0); FMA4P(c0B, c1B, pk1(pb.y), k1);
                FMA4P(c0B, c1B, pk1(pb.z), k2); FMA4P(c0B, c1B, pk1(pb.w), k3);
            }
            st4u(sm + OFF_X + rA * 64 + e4, c0A, c1A);
            st4u(sm + OFF_X + (rA+1) * 64 + e4, c0B, c1B);
            __syncwarp();
        }
    }
    __syncthreads();

    // ============ Stage 3: QKV projection ==================================
    for (int idx = tid; idx < 192 * 64; idx += NTHR) {
        const int e = idx >> 6, d = idx & 63;
        sm[OFF_W + d * 196 + e] = w_qkv[idx];     // wT[d][e], stride 196
    }
    __syncthreads();
    {
        const float4 bq0 = ld4(b_qkv + e4), bq1 = ld4(b_qkv + 64 + e4),
                     bq2 = ld4(b_qkv + 128 + e4);
#pragma unroll 1
        for (int g = warp; g < NT / 4; g += NWARP) {
            const int rA = g * 4 + hh2;
            const float* xA = sm + OFF_X + rA * 64;
            const float* xB = xA + 64;
            u64 q0A = pk2(bq0.x, bq0.y), q1A = pk2(bq0.z, bq0.w);
            u64 k0A = pk2(bq1.x, bq1.y), k1A = pk2(bq1.z, bq1.w);
            u64 v0A = pk2(bq2.x, bq2.y), v1A = pk2(bq2.z, bq2.w);
            u64 q0B = q0A, q1B = q1A, k0B = k0A, k1B = k1A, v0B = v0A, v1B = v1A;
#pragma unroll 4
            for (int d = 0; d < 64; d += 4) {
                const float4 a = ld4(xA + d), b = ld4(xB + d);
#define QKV_STEP(xa, xb, dd) { \
                const float* wp = sm + OFF_W + (d + dd) * 196 + e4; \
                const ulonglong2 w0 = ld4u(wp), w1 = ld4u(wp + 64), w2 = ld4u(wp + 128); \
                const u64 sa = pk1(xa), sb = pk1(xb); \
                FMA4P(q0A, q1A, sa, w0); FMA4P(k0A, k1A, sa, w1); FMA4P(v0A, v1A, sa, w2); \
                FMA4P(q0B, q1B, sb, w0); FMA4P(k0B, k1B, sb, w1); FMA4P(v0B, v1B, sb, w2); }
                QKV_STEP(a.x, b.x, 0) QKV_STEP(a.y, b.y, 1)
                QKV_STEP(a.z, b.z, 2) QKV_STEP(a.w, b.w, 3)
#undef QKV_STEP
            }
            st4u(sm + OFF_X + rA * 64 + e4, q0A, q1A);      // q overwrites x
            st4u(sm + OFF_X + (rA+1) * 64 + e4, q0B, q1B);
            st4u(sm + OFF_K + rA * 68 + e4, k0A, k1A);
            st4u(sm + OFF_K + (rA+1) * 68 + e4, k0B, k1B);
            st4u(sm + OFF_V + rA * 68 + e4, v0A, v1A);
            st4u(sm + OFF_V + (rA+1) * 68 + e4, v0B, v1B);
        }
    }
    __syncthreads();

    // ============ Stage 4: 4-head self-attention (o overwrites q) ==========
    {
        float* P  = sm + OFF_W + warp * 832;          // [4][208]
        float* pA = P + hh2 * 208;
        float* pB = pA + 208;
        const int ms = et >> 2, dd4 = (et & 3) * 4;
#pragma unroll 1
        for (int g = warp; g < NT / 4; g += NWARP) {
            const int rA = g * 4 + hh2;
            if (et < 8) { pA[200 + et] = 0.f; pB[200 + et] = 0.f; }
#pragma unroll 1
            for (int hd0 = 0; hd0 < 64; hd0 += 16) {
                const float* qA = sm + OFF_X + rA * 64 + hd0;
                const float* qB = qA + 64;
                float lA[13], lB[13];
#pragma unroll
                for (int j = 0; j < 13; ++j) { lA[j] = 0.f; lB[j] = 0.f; }
#pragma unroll
                for (int d = 0; d < 16; d += 4) {
                    const float4 a = ld4(qA + d), b = ld4(qB + d);
#pragma unroll
                    for (int j = 0; j < 13; ++j) {
                        const float4 kv = ld4(sm + OFF_K + (et + 16*j) * 68 + hd0 + d);
                        lA[j] = dot4(a, kv, lA[j]);
                        lB[j] = dot4(b, kv, lB[j]);
                    }
                }
                float mA = -1e30f, mB = -1e30f;
#pragma unroll
                for (int j = 0; j < 13; ++j) {
                    const bool ok = et + 16*j < NT;
                    lA[j] = ok ? lA[j] * 0.25f : -1e30f;
                    lB[j] = ok ? lB[j] * 0.25f : -1e30f;
                    mA = fmaxf(mA, lA[j]); mB = fmaxf(mB, lB[j]);
                }
                mA = hmax16(mA); mB = hmax16(mB);
                float sA = 0.f, sB = 0.f;
#pragma unroll
                for (int j = 0; j < 13; ++j) {
                    const bool ok = et + 16*j < NT;
                    lA[j] = ok ? __expf(lA[j] - mA) : 0.f;
                    lB[j] = ok ? __expf(lB[j] - mB) : 0.f;
                    sA += lA[j]; sB += lB[j];
                }
                const float iA = 1.f / hsum16(sA), iB = 1.f / hsum16(sB);
#pragma unroll
                for (int j = 0; j < 13; ++j) {
                    const int m = et + 16*j;
                    if (m < NT) { pA[m] = lA[j] * iA; pB[m] = lB[j] * iB; }
                }
                __syncwarp();
                u64 o0A = 0, o1A = 0, o0B = 0, o1B = 0;
                const int m0 = ms * 52;
#pragma unroll
                for (int mi = 0; mi < 52; mi += 4) {
                    const int m = m0 + mi;
                    const float4 pa = ld4(pA + m), pb = ld4(pB + m);
                    const float* vp = sm + OFF_V + m * 68 + hd0 + dd4;
                    const ulonglong2 v0 = ld4u(vp),       v1 = ld4u(vp + 68),
                                     v2 = ld4u(vp + 136), v3 = ld4u(vp + 204);
                    FMA4P(o0A, o1A, pk1(pa.x), v0); FMA4P(o0A, o1A, pk1(pa.y), v1);
                    FMA4P(o0A, o1A, pk1(pa.z), v2); FMA4P(o0A, o1A, pk1(pa.w), v3);
                    FMA4P(o0B, o1B, pk1(pb.x), v0); FMA4P(o0B, o1B, pk1(pb.y), v1);
                    FMA4P(o0B, o1B, pk1(pb.z), v2); FMA4P(o0B, o1B, pk1(pb.w), v3);
                }
                float4 oA, oB;
                upk(o0A, oA.x, oA.y); upk(o1A, oA.z, oA.w);
                upk(o0B, oB.x, oB.y); upk(o1B, oB.z, oB.w);
#define RED48(c) { c += __shfl_xor_sync(0xffffffffu, c, 4); \
                   c += __shfl_xor_sync(0xffffffffu, c, 8); }
                RED48(oA.x) RED48(oA.y) RED48(oA.z) RED48(oA.w)
                RED48(oB.x) RED48(oB.y) RED48(oB.z) RED48(oB.w)
#undef RED48
                if (ms == 0) {
                    st4(sm + OFF_X + rA * 64 + hd0 + dd4, oA);
                    st4(sm + OFF_X + (rA+1) * 64 + hd0 + dd4, oB);
                }
                __syncwarp();
            }
        }
    }
    __syncthreads();

    // ============ Stage 5: attn_out -> out_proj + residual =================
    for (int idx = tid; idx < 64 * 64; idx += NTHR) {
        const int e = idx >> 6, d = idx & 63;
        sm[OFF_W + d * 68 + e] = w_ao[idx];           // aoT[d][e], stride 68
    }
    for (int idx = tid; idx < 256 * 64; idx += NTHR) {
        const int c = idx >> 6, e = idx & 63;
        sm[OFF_K + e * 260 + c] = w_op[idx];          // opT[e][c], stride 260
    }
    __syncthreads();
    {
        const float4 bao  = ld4(b_ao + e4);
        const float4 bop0 = ld4(b_op + e4),       bop1 = ld4(b_op + 64 + e4),
                     bop2 = ld4(b_op + 128 + e4), bop3 = ld4(b_op + 192 + e4);
        float* Abuf = sm + OFF_W + 4352 + warp * 288;
#pragma unroll 1
        for (int g = warp; g < NT / 4; g += NWARP) {
            const int rA = g * 4 + hh2;
            const float* oA = sm + OFF_X + rA * 64;
            const float* oB = oA + 64;
            u64 a0A = pk2(bao.x, bao.y), a1A = pk2(bao.z, bao.w);
            u64 a0B = a0A, a1B = a1A;
#pragma unroll 4
            for (int d = 0; d < 64; d += 4) {
                const float4 a = ld4(oA + d), b = ld4(oB + d);
                const float* wp = sm + OFF_W + d * 68 + e4;
                const ulonglong2 w0 = ld4u(wp),       w1 = ld4u(wp + 68),
                                 w2 = ld4u(wp + 136), w3 = ld4u(wp + 204);
                FMA4P(a0A, a1A, pk1(a.x), w0); FMA4P(a0A, a1A, pk1(a.y), w1);
                FMA4P(a0A, a1A, pk1(a.z), w2); FMA4P(a0A, a1A, pk1(a.w), w3);
                FMA4P(a0B, a1B, pk1(b.x), w0); FMA4P(a0B, a1B, pk1(b.y), w1);
                FMA4P(a0B, a1B, pk1(b.z), w2); FMA4P(a0B, a1B, pk1(b.w), w3);
            }
            st4u(Abuf + hh2 * 68 + e4, a0A, a1A);
            st4u(Abuf + hh2 * 68 + 68 + e4, a0B, a1B);
            __syncwarp();
            const float* tA = turb_s + (size_t)rA * CM;
            const float* tB = tA + CM;
            float* outA = out_s + (size_t)rA * CM;
            float* outB = outA + CM;
            u64 aA[8], aB[8];
            {
                float4 r;
                r = ld4(tA + e4);
                aA[0] = pk2(bop0.x + r.x, bop0.y + r.y); aA[1] = pk2(bop0.z + r.z, bop0.w + r.w);
                r = ld4(tA + 64 + e4);
                aA[2] = pk2(bop1.x + r.x, bop1.y + r.y); aA[3] = pk2(bop1.z + r.z, bop1.w + r.w);
                r = ld4(tA + 128 + e4);
                aA[4] = pk2(bop2.x + r.x, bop2.y + r.y); aA[5] = pk2(bop2.z + r.z, bop2.w + r.w);
                r = ld4(tA + 192 + e4);
                aA[6] = pk2(bop3.x + r.x, bop3.y + r.y); aA[7] = pk2(bop3.z + r.z, bop3.w + r.w);
                r = ld4(tB + e4);
                aB[0] = pk2(bop0.x + r.x, bop0.y + r.y); aB[1] = pk2(bop0.z + r.z, bop0.w + r.w);
                r = ld4(tB + 64 + e4);
                aB[2] = pk2(bop1.x + r.x, bop1.y + r.y); aB[3] = pk2(bop1.z + r.z, bop1.w + r.w);
                r = ld4(tB + 128 + e4);
                aB[4] = pk2(bop2.x + r.x, bop2.y + r.y); aB[5] = pk2(bop2.z + r.z, bop2.w + r.w);
                r = ld4(tB + 192 + e4);
                aB[6] = pk2(bop3.x + r.x, bop3.y + r.y); aB[7] = pk2(bop3.z + r.z, bop3.w + r.w);
            }
            const float* arowA = Abuf + hh2 * 68;
            const float* arowB = arowA + 68;
#pragma unroll 2
            for (int e = 0; e < 64; e += 4) {
                const float4 a = ld4(arowA + e), b = ld4(arowB + e);
#define OP_STEP(xa, xb, ee) { \
                const float* wp = sm + OFF_K + (e + ee) * 260 + e4; \
                const ulonglong2 w0 = ld4u(wp),       w1 = ld4u(wp + 64), \
                                 w2 = ld4u(wp + 128), w3 = ld4u(wp + 192); \
                const u64 sa = pk1(xa), sb = pk1(xb); \
                FMA4P(aA[0], aA[1], sa, w0); FMA4P(aA[2], aA[3], sa, w1); \
                FMA4P(aA[4], aA[5], sa, w2); FMA4P(aA[6], aA[7], sa, w3); \
                FMA4P(aB[0], aB[1], sb, w0); FMA4P(aB[2], aB[3], sb, w1); \
                FMA4P(aB[4], aB[5], sb, w2); FMA4P(aB[6], aB[7], sb, w3); }
                OP_STEP(a.x, b.x, 0) OP_STEP(a.y, b.y, 1)
                OP_STEP(a.z, b.z, 2) OP_STEP(a.w, b.w, 3)
#undef OP_STEP
            }
            st4u(outA + e4,       aA[0], aA[1]); st4u(outA + 64 + e4,  aA[2], aA[3]);
            st4u(outA + 128 + e4, aA[4], aA[5]); st4u(outA + 192 + e4, aA[6], aA[7]);
            st4u(outB + e4,       aB[0], aB[1]); st4u(outB + 64 + e4,  aB[2], aB[3]);
            st4u(outB + 128 + e4, aB[4], aB[5]); st4u(outB + 192 + e4, aB[6], aB[7]);
            __syncwarp();
        }
    }
}

extern "C" void kernel_launch(void* const* d_in, const int* in_sizes, int n_in,
                              void* d_out, int out_size)
{
    const float* turb  = (const float*)d_in[0];
    const float* weath = (const float*)d_in[1];
    const float* w_t   = (const float*)d_in[2];
    const float* b_t   = (const float*)d_in[3];
    const float* w_w   = (const float*)d_in[4];
    const float* b_w   = (const float*)d_in[5];
    const float* g_t   = (const float*)d_in[6];
    const float* be_t  = (const float*)d_in[7];
    const float* g_w   = (const float*)d_in[8];
    const float* be_w  = (const float*)d_in[9];
    const float* w_qkv = (const float*)d_in[10];
    const float* b_qkv = (const float*)d_in[11];
    const float* w_ao  = (const float*)d_in[12];
    const float* b_ao  = (const float*)d_in[13];
    const float* w_op  = (const float*)d_in[14];
    const float* b_op  = (const float*)d_in[15];
    float* out = (float*)d_out;

    const int S = in_sizes[0] / (NT * CM);   // 768
    const size_t smem = (size_t)SMEM_F * sizeof(float);
    cudaFuncSetAttribute(wda_kernel, cudaFuncAttributeMaxDynamicSharedMemorySize,
                         (int)smem);
    wda_kernel<<<S, NTHR, smem>>>(turb, weath, w_t, b_t, w_w, b_w,
                                  g_t, be_t, g_w, be_w, w_qkv, b_qkv,
                                  w_ao, b_ao, w_op, b_op, out);
}